// round 6
// baseline (speedup 1.0000x reference)
#include <cuda_runtime.h>
#include <cuda_bf16.h>
#include <math.h>
#include <stdint.h>

#define D_MODEL 1024
#define N_HEADS 16
#define HEAD_DIM 64
#define BATCH 2
#define SEQ 2048
#define BS_TOT (BATCH * SEQ)
#define QKV_ELEMS (BATCH * N_HEADS * SEQ * HEAD_DIM)

__device__ float g_q[QKV_ELEMS];
__device__ float g_k[QKV_ELEMS];
__device__ float g_v[QKV_ELEMS];
__device__ float g_ctx[BS_TOT * D_MODEL];
__device__ float g_cos_t[SEQ * 32];
__device__ float g_sin_t[SEQ * 32];

// ---------------------------------------------------------------------------
__device__ __forceinline__ unsigned f2tf(float x) {
    unsigned r;
    asm("cvt.rna.tf32.f32 %0, %1;" : "=r"(r) : "f"(x));
    return r;
}

__device__ __forceinline__ void mma_tf32(float* c, unsigned a0, unsigned a1,
                                         unsigned a2, unsigned a3,
                                         unsigned b0, unsigned b1) {
    asm volatile(
        "mma.sync.aligned.m16n8k8.row.col.f32.tf32.tf32.f32 "
        "{%0,%1,%2,%3}, {%4,%5,%6,%7}, {%8,%9}, {%0,%1,%2,%3};\n"
        : "+f"(c[0]), "+f"(c[1]), "+f"(c[2]), "+f"(c[3])
        : "r"(a0), "r"(a1), "r"(a2), "r"(a3), "r"(b0), "r"(b1));
}

// exp(x) for x <= 0 on fma/alu pipes only (no MUFU)
__device__ __forceinline__ float exp_fast(float x) {
    float y = x * 1.4426950408889634f;
    y = fmaxf(y, -126.0f);
    float tt = y + 12582912.0f;
    int   n = __float_as_int(tt) - 0x4B400000;
    float f = y - (tt - 12582912.0f);
    float p = 1.33978308e-3f;
    p = fmaf(p, f, 9.61812910e-3f);
    p = fmaf(p, f, 5.55041087e-2f);
    p = fmaf(p, f, 2.40226507e-1f);
    p = fmaf(p, f, 6.93147181e-1f);
    p = fmaf(p, f, 1.0f);
    return p * __int_as_float((n + 127) << 23);
}

__device__ __forceinline__ void cpa16(uint32_t saddr, const void* gaddr) {
    asm volatile("cp.async.cg.shared.global [%0], [%1], 16;\n"
                 :: "r"(saddr), "l"(gaddr));
}
__device__ __forceinline__ void cpa_commit() {
    asm volatile("cp.async.commit_group;\n");
}
template <int N>
__device__ __forceinline__ void cpa_wait() {
    asm volatile("cp.async.wait_group %0;\n" :: "n"(N));
}

// ---------------------------------------------------------------------------
// RoPE table (fp64 once). token_positions may be int64 or int32; sniff it.
// ---------------------------------------------------------------------------
__global__ void rope_table_kernel(const int* __restrict__ pos_raw) {
    int idx = blockIdx.x * blockDim.x + threadIdx.x;
    if (idx >= SEQ * 32) return;
    int s = idx >> 5;
    int p = idx & 31;
    bool is64 = (pos_raw[1] == 0 && pos_raw[3] == 0 && pos_raw[5] == 0);
    long long pos = is64 ? ((const long long*)pos_raw)[s] : (long long)pos_raw[s];
    double inv = exp(-(double)p * 0.28782313662425572);
    double f = (double)pos * inv;
    g_cos_t[idx] = (float)cos(f);
    g_sin_t[idx] = (float)sin(f);
}

// ---------------------------------------------------------------------------
// NT GEMM via tf32 mma.sync. CTA 128x128, kTile 16, double-buffered smem.
// 128 threads = 4 warps in a 2x2 grid of 64x64 warp tiles:
//   - A smem redundancy 2 (was 4), frag-LDS per MMA = 1.0 (was 1.5)
// mode = mode_base + blockIdx.z:
//   0: g_q + RoPE   1: g_k + RoPE   2: g_v   3: A=g_ctx -> Cout
// ---------------------------------------------------------------------------
__global__ __launch_bounds__(128, 2) void gemm_all(const float* __restrict__ x,
                                                   const float* __restrict__ w0,
                                                   const float* __restrict__ w1,
                                                   const float* __restrict__ w2,
                                                   float* __restrict__ Cout,
                                                   int mode_base) {
    const int K = D_MODEL;
    int mode = mode_base + blockIdx.z;
    const float* A  = (mode == 3) ? g_ctx : x;
    const float* Bw = (mode == 1) ? w1 : (mode == 2) ? w2 : w0;

    __shared__ unsigned As[2][128 * 20];   // [row][k] stride 20, conflict-free
    __shared__ unsigned Bs[2][128 * 20];

    int tid = threadIdx.x;
    int warp = tid >> 5, lane = tid & 31;
    int g = lane >> 2, t = lane & 3;
    int wm = warp >> 1, wn = warp & 1;     // 2m x 2n grid of 64x64 warp tiles
    int m0 = blockIdx.y * 128;
    int n0 = blockIdx.x * 128;

    float acc[4][8][4];
#pragma unroll
    for (int i = 0; i < 4; i++)
#pragma unroll
        for (int j = 0; j < 8; j++)
#pragma unroll
            for (int r = 0; r < 4; r++) acc[i][j][r] = 0.0f;

    // loader: each thread owns one row (tid), 16 k per tile = 4 float4
    const float* Ap = A + (size_t)(m0 + tid) * K;
    const float* Bp = Bw + (size_t)(n0 + tid) * K;

    // prologue: k-tile 0 -> stage 0
#pragma unroll
    for (int i = 0; i < 4; i++) {
        float4 a = *(const float4*)(Ap + 4 * i);
        float4 b = *(const float4*)(Bp + 4 * i);
        uint4 ua, ub;
        ua.x = f2tf(a.x); ua.y = f2tf(a.y); ua.z = f2tf(a.z); ua.w = f2tf(a.w);
        ub.x = f2tf(b.x); ub.y = f2tf(b.y); ub.z = f2tf(b.z); ub.w = f2tf(b.w);
        *(uint4*)&As[0][tid * 20 + 4 * i] = ua;
        *(uint4*)&Bs[0][tid * 20 + 4 * i] = ub;
    }
    __syncthreads();

    int cur = 0;
    for (int kt = 0; kt < K; kt += 16) {
        bool hasNext = (kt + 16) < K;
        float4 pa[4], pb[4];
        if (hasNext) {
#pragma unroll
            for (int i = 0; i < 4; i++) {
                pa[i] = *(const float4*)(Ap + kt + 16 + 4 * i);
                pb[i] = *(const float4*)(Bp + kt + 16 + 4 * i);
            }
        }
#pragma unroll
        for (int ks = 0; ks < 16; ks += 8) {
            unsigned af[4][4];
#pragma unroll
            for (int mt = 0; mt < 4; mt++) {
                int row = wm * 64 + mt * 16;
                af[mt][0] = As[cur][(row + g) * 20 + ks + t];
                af[mt][1] = As[cur][(row + g + 8) * 20 + ks + t];
                af[mt][2] = As[cur][(row + g) * 20 + ks + t + 4];
                af[mt][3] = As[cur][(row + g + 8) * 20 + ks + t + 4];
            }
            unsigned bf[8][2];
#pragma unroll
            for (int nt = 0; nt < 8; nt++) {
                int col = wn * 64 + nt * 8;
                bf[nt][0] = Bs[cur][(col + g) * 20 + ks + t];
                bf[nt][1] = Bs[cur][(col + g) * 20 + ks + t + 4];
            }
#pragma unroll
            for (int mt = 0; mt < 4; mt++)
#pragma unroll
                for (int nt = 0; nt < 8; nt++)
                    mma_tf32(acc[mt][nt], af[mt][0], af[mt][1], af[mt][2], af[mt][3],
                             bf[nt][0], bf[nt][1]);
        }
        if (hasNext) {
            int nxt = cur ^ 1;
#pragma unroll
            for (int i = 0; i < 4; i++) {
                uint4 ua, ub;
                ua.x = f2tf(pa[i].x); ua.y = f2tf(pa[i].y);
                ua.z = f2tf(pa[i].z); ua.w = f2tf(pa[i].w);
                ub.x = f2tf(pb[i].x); ub.y = f2tf(pb[i].y);
                ub.z = f2tf(pb[i].z); ub.w = f2tf(pb[i].w);
                *(uint4*)&As[nxt][tid * 20 + 4 * i] = ua;
                *(uint4*)&Bs[nxt][tid * 20 + 4 * i] = ub;
            }
        }
        __syncthreads();
        cur ^= 1;
    }

    if (mode == 3) {
#pragma unroll
        for (int mt = 0; mt < 4; mt++) {
            int m = m0 + wm * 64 + mt * 16 + g;
#pragma unroll
            for (int nt = 0; nt < 8; nt++) {
                int col = n0 + wn * 64 + nt * 8 + 2 * t;
                *(float2*)(Cout + (size_t)m * D_MODEL + col) =
                    make_float2(acc[mt][nt][0], acc[mt][nt][1]);
                *(float2*)(Cout + (size_t)(m + 8) * D_MODEL + col) =
                    make_float2(acc[mt][nt][2], acc[mt][nt][3]);
            }
        }
    } else {
        float* dst = (mode == 0) ? g_q : (mode == 1) ? g_k : g_v;
        bool do_rope = (mode != 2);
#pragma unroll
        for (int mt = 0; mt < 4; mt++) {
            int mA = m0 + wm * 64 + mt * 16 + g;
            int mB = mA + 8;
            int bA = mA >> 11, sA = mA & (SEQ - 1);
            int bB = mB >> 11, sB = mB & (SEQ - 1);
#pragma unroll
            for (int nt = 0; nt < 8; nt++) {
                int col = n0 + wn * 64 + nt * 8 + 2 * t;
                int h = col >> 6, dd = col & 63, p = dd >> 1;
                float x0 = acc[mt][nt][0], x1 = acc[mt][nt][1];
                float x2 = acc[mt][nt][2], x3 = acc[mt][nt][3];
                if (do_rope) {
                    float cA = g_cos_t[sA * 32 + p], nA = g_sin_t[sA * 32 + p];
                    float cB = g_cos_t[sB * 32 + p], nB = g_sin_t[sB * 32 + p];
                    float e0 = x0 * cA - x1 * nA, o0 = x0 * nA + x1 * cA;
                    float e1 = x2 * cB - x3 * nB, o1 = x2 * nB + x3 * cB;
                    x0 = e0; x1 = o0; x2 = e1; x3 = o1;
                }
                *(float2*)(dst + (((size_t)bA * N_HEADS + h) * SEQ + sA) * HEAD_DIM + dd) =
                    make_float2(x0, x1);
                *(float2*)(dst + (((size_t)bB * N_HEADS + h) * SEQ + sB) * HEAD_DIM + dd) =
                    make_float2(x2, x3);
            }
        }
    }
}

// ---------------------------------------------------------------------------
// Flash attention (causal), tf32 mma. (unchanged from R5 passing version)
// CTA = 128 queries x (b,h); 128 threads = 4 warps; Q persistent in registers.
// K/V staged fp32 via cp.async; KV tiles of 64.
// ---------------------------------------------------------------------------
__global__ __launch_bounds__(128) void flash_tc() {
    __shared__ float Ks[64 * 68];
    __shared__ float Vs[64 * 72];

    int qb = blockIdx.x;
    int bh = blockIdx.y;
    int tid = threadIdx.x;
    int warp = tid >> 5, lane = tid & 31;
    int g = lane >> 2, t = lane & 3;

    const float* qp = g_q + ((size_t)bh * SEQ + qb * 128) * HEAD_DIM;
    const float* kp0 = g_k + (size_t)bh * SEQ * HEAD_DIM;
    const float* vp0 = g_v + (size_t)bh * SEQ * HEAD_DIM;

    uint32_t ksb = (uint32_t)__cvta_generic_to_shared(Ks);
    uint32_t vsb = (uint32_t)__cvta_generic_to_shared(Vs);

    unsigned qf[2][8][4];
#pragma unroll
    for (int mf = 0; mf < 2; mf++) {
        int r0 = warp * 32 + mf * 16 + g;
#pragma unroll
        for (int ks = 0; ks < 8; ks++) {
            qf[mf][ks][0] = f2tf(qp[(size_t)r0 * 64 + ks * 8 + t] * 0.125f);
            qf[mf][ks][1] = f2tf(qp[(size_t)(r0 + 8) * 64 + ks * 8 + t] * 0.125f);
            qf[mf][ks][2] = f2tf(qp[(size_t)r0 * 64 + ks * 8 + t + 4] * 0.125f);
            qf[mf][ks][3] = f2tf(qp[(size_t)(r0 + 8) * 64 + ks * 8 + t + 4] * 0.125f);
        }
    }

    float oacc[2][8][4];
#pragma unroll
    for (int mf = 0; mf < 2; mf++)
#pragma unroll
        for (int i = 0; i < 8; i++)
#pragma unroll
            for (int r = 0; r < 4; r++) oacc[mf][i][r] = 0.0f;
    float mst[4], lst[4];
#pragma unroll
    for (int i = 0; i < 4; i++) { mst[i] = -1e30f; lst[i] = 0.0f; }

    int kbmax = 2 * qb + 1;

    {
        const float* kb_base = kp0;
#pragma unroll
        for (int i = 0; i < 8; i++) {
            int j = tid + 128 * i;
            int r = j >> 4, c = j & 15;
            cpa16(ksb + r * 272 + c * 16, kb_base + r * 64 + c * 4);
        }
        cpa_commit();
    }

    for (int kb = 0; kb <= kbmax; kb++) {
        __syncthreads();
        {
            const float* vb_base = vp0 + (size_t)kb * 64 * 64;
#pragma unroll
            for (int i = 0; i < 8; i++) {
                int j = tid + 128 * i;
                int r = j >> 4, c = j & 15;
                cpa16(vsb + r * 288 + c * 16, vb_base + r * 64 + c * 4);
            }
            cpa_commit();
        }
        cpa_wait<1>();
        __syncthreads();

        float sacc[2][8][4];
#pragma unroll
        for (int mf = 0; mf < 2; mf++)
#pragma unroll
            for (int i = 0; i < 8; i++)
#pragma unroll
                for (int r = 0; r < 4; r++) sacc[mf][i][r] = 0.0f;

#pragma unroll
        for (int ks = 0; ks < 8; ks++) {
#pragma unroll
            for (int nt = 0; nt < 8; nt++) {
                unsigned b0 = f2tf(Ks[(nt * 8 + g) * 68 + ks * 8 + t]);
                unsigned b1 = f2tf(Ks[(nt * 8 + g) * 68 + ks * 8 + t + 4]);
                mma_tf32(sacc[0][nt], qf[0][ks][0], qf[0][ks][1], qf[0][ks][2],
                         qf[0][ks][3], b0, b1);
                mma_tf32(sacc[1][nt], qf[1][ks][0], qf[1][ks][1], qf[1][ks][2],
                         qf[1][ks][3], b0, b1);
            }
        }

        if (kb >= 2 * qb) {
#pragma unroll
            for (int mf = 0; mf < 2; mf++) {
                int rA = qb * 128 + warp * 32 + mf * 16 + g;
                int rB = rA + 8;
#pragma unroll
                for (int nt = 0; nt < 8; nt++) {
                    int c0 = kb * 64 + nt * 8 + 2 * t;
                    if (c0 > rA) sacc[mf][nt][0] = -1e30f;
                    if (c0 + 1 > rA) sacc[mf][nt][1] = -1e30f;
                    if (c0 > rB) sacc[mf][nt][2] = -1e30f;
                    if (c0 + 1 > rB) sacc[mf][nt][3] = -1e30f;
                }
            }
        }

#pragma unroll
        for (int mf = 0; mf < 2; mf++) {
            float mxA = -1e30f, mxB = -1e30f;
#pragma unroll
            for (int nt = 0; nt < 8; nt++) {
                mxA = fmaxf(mxA, fmaxf(sacc[mf][nt][0], sacc[mf][nt][1]));
                mxB = fmaxf(mxB, fmaxf(sacc[mf][nt][2], sacc[mf][nt][3]));
            }
            mxA = fmaxf(mxA, __shfl_xor_sync(0xffffffffu, mxA, 1));
            mxA = fmaxf(mxA, __shfl_xor_sync(0xffffffffu, mxA, 2));
            mxB = fmaxf(mxB, __shfl_xor_sync(0xffffffffu, mxB, 1));
            mxB = fmaxf(mxB, __shfl_xor_sync(0xffffffffu, mxB, 2));
            float nmA = fmaxf(mst[mf * 2], mxA);
            float nmB = fmaxf(mst[mf * 2 + 1], mxB);
            float aA = exp_fast(mst[mf * 2] - nmA);
            float aB = exp_fast(mst[mf * 2 + 1] - nmB);
            mst[mf * 2] = nmA; mst[mf * 2 + 1] = nmB;

            float rsA = 0.0f, rsB = 0.0f;
#pragma unroll
            for (int nt = 0; nt < 8; nt++) {
                float p0 = exp_fast(sacc[mf][nt][0] - nmA);
                float p1 = exp_fast(sacc[mf][nt][1] - nmA);
                float p2 = exp_fast(sacc[mf][nt][2] - nmB);
                float p3 = exp_fast(sacc[mf][nt][3] - nmB);
                rsA += p0 + p1;
                rsB += p2 + p3;
                sacc[mf][nt][0] = __uint_as_float(f2tf(p0));
                sacc[mf][nt][1] = __uint_as_float(f2tf(p1));
                sacc[mf][nt][2] = __uint_as_float(f2tf(p2));
                sacc[mf][nt][3] = __uint_as_float(f2tf(p3));
            }
            rsA += __shfl_xor_sync(0xffffffffu, rsA, 1);
            rsA += __shfl_xor_sync(0xffffffffu, rsA, 2);
            rsB += __shfl_xor_sync(0xffffffffu, rsB, 1);
            rsB += __shfl_xor_sync(0xffffffffu, rsB, 2);
            lst[mf * 2] = lst[mf * 2] * aA + rsA;
            lst[mf * 2 + 1] = lst[mf * 2 + 1] * aB + rsB;
#pragma unroll
            for (int nt = 0; nt < 8; nt++) {
                oacc[mf][nt][0] *= aA; oacc[mf][nt][1] *= aA;
                oacc[mf][nt][2] *= aB; oacc[mf][nt][3] *= aB;
            }
        }

        __syncthreads();
        if (kb < kbmax) {
            const float* kb_base = kp0 + (size_t)(kb + 1) * 64 * 64;
#pragma unroll
            for (int i = 0; i < 8; i++) {
                int j = tid + 128 * i;
                int r = j >> 4, c = j & 15;
                cpa16(ksb + r * 272 + c * 16, kb_base + r * 64 + c * 4);
            }
        }
        cpa_commit();
        cpa_wait<1>();
        __syncthreads();

        int srcA = (lane & ~3) | (t >> 1);
        int srcB = srcA + 2;
        bool odd = (t & 1);
#pragma unroll
        for (int kt = 0; kt < 8; kt++) {
            unsigned a[2][4];
#pragma unroll
            for (int mf = 0; mf < 2; mf++) {
                float v00 = __shfl_sync(0xffffffffu, sacc[mf][kt][0], srcA);
                float v01 = __shfl_sync(0xffffffffu, sacc[mf][kt][1], srcA);
                float v10 = __shfl_sync(0xffffffffu, sacc[mf][kt][2], srcA);
                float v11 = __shfl_sync(0xffffffffu, sacc[mf][kt][3], srcA);
                float w00 = __shfl_sync(0xffffffffu, sacc[mf][kt][0], srcB);
                float w01 = __shfl_sync(0xffffffffu, sacc[mf][kt][1], srcB);
                float w10 = __shfl_sync(0xffffffffu, sacc[mf][kt][2], srcB);
                float w11 = __shfl_sync(0xffffffffu, sacc[mf][kt][3], srcB);
                a[mf][0] = __float_as_uint(odd ? v01 : v00);
                a[mf][1] = __float_as_uint(odd ? v11 : v10);
                a[mf][2] = __float_as_uint(odd ? w01 : w00);
                a[mf][3] = __float_as_uint(odd ? w11 : w10);
            }
#pragma unroll
            for (int nt = 0; nt < 8; nt++) {
                unsigned b0 = f2tf(Vs[(kt * 8 + t) * 72 + nt * 8 + g]);
                unsigned b1 = f2tf(Vs[(kt * 8 + t + 4) * 72 + nt * 8 + g]);
                mma_tf32(oacc[0][nt], a[0][0], a[0][1], a[0][2], a[0][3], b0, b1);
                mma_tf32(oacc[1][nt], a[1][0], a[1][1], a[1][2], a[1][3], b0, b1);
            }
        }
    }

    int b = bh >> 4, h = bh & 15;
#pragma unroll
    for (int mf = 0; mf < 2; mf++) {
        float iA = 1.0f / lst[mf * 2];
        float iB = 1.0f / lst[mf * 2 + 1];
        int rowA = qb * 128 + warp * 32 + mf * 16 + g;
        int rowB = rowA + 8;
#pragma unroll
        for (int nt = 0; nt < 8; nt++) {
            int col = h * 64 + nt * 8 + 2 * t;
            *(float2*)(g_ctx + ((size_t)b * SEQ + rowA) * D_MODEL + col) =
                make_float2(oacc[mf][nt][0] * iA, oacc[mf][nt][1] * iA);
            *(float2*)(g_ctx + ((size_t)b * SEQ + rowB) * D_MODEL + col) =
                make_float2(oacc[mf][nt][2] * iB, oacc[mf][nt][3] * iB);
        }
    }
}

// ---------------------------------------------------------------------------
extern "C" void kernel_launch(void* const* d_in, const int* in_sizes, int n_in,
                              void* d_out, int out_size) {
    const float* x  = (const float*)d_in[0];
    const float* wq = (const float*)d_in[1];
    const float* wk = (const float*)d_in[2];
    const float* wv = (const float*)d_in[3];
    const float* wo = (const float*)d_in[4];
    const int* pos  = (const int*)d_in[5];
    float* out = (float*)d_out;

    rope_table_kernel<<<(SEQ * 32 + 255) / 256, 256>>>(pos);

    dim3 gq(D_MODEL / 128, BS_TOT / 128, 3);   // fused QKV
    gemm_all<<<gq, 128>>>(x, wq, wk, wv, nullptr, 0);

    dim3 fg(SEQ / 128, BATCH * N_HEADS);
    flash_tc<<<fg, 128>>>();

    dim3 gg(D_MODEL / 128, BS_TOT / 128, 1);   // out projection
    gemm_all<<<gg, 128>>>(nullptr, wo, nullptr, nullptr, out, 3);
}